// round 2
// baseline (speedup 1.0000x reference)
#include <cuda_runtime.h>
#include <cuda_fp16.h>
#include <math.h>
#include <stdint.h>

// ---------------- problem constants ----------------
#define BB   4
#define NSP  1500
#define NN   6000          // BB*NSP
#define EE   120000
#define HH   384
#define HWPX (HH*HH)       // 147456
#define NPX  (BB*HWPX)     // 589824
#define HS   96
#define HWI  (HS*HS)       // 9216
#define CC   256
#define NPOOL 512          // feats0 | feats1 columns
#define NENT (4*NPX)       // 2359296 pooling entries
#define CSR_E (EE+NN)      // folded self loops: one entry, weight 2*dis^2
#define SIGMA_INV 5.0f     // 1/0.2

// ---------------- scratch (device globals; no allocation) ----------------
__device__ __half g_Bmh[(size_t)BB*HWI*NPOOL];   // 37.7 MB feats NHWC fp16, stacked
__device__ int2  g_ent[NENT];                    // packed (row, w-bits) 18.9 MB
__device__ float g_pool[(size_t)NN*NPOOL];       // pooled sums (pre-division)
__device__ float g_Za[NN*CC];
__device__ float g_Zb[NN*CC];
__device__ float g_xw[NN*CC];
__device__ float g_cnt[NN];
__device__ float g_sumI[NN*3];
__device__ float g_deg[NN];
__device__ float g_dis[NN];
__device__ float g_wnn[EE];
__device__ int   g_icnt[NN];
__device__ int   g_ecnt[NN];
__device__ int   g_eoff[NN+1];
__device__ int   g_poff[NN+1];
__device__ int   g_efill[NN];
__device__ int   g_pfill[NN];
__device__ int   g_csr_src[CSR_E];
__device__ float g_csr_nrm[CSR_E];
__device__ float g_wn[15*CC];

// ---------------- init ----------------
__global__ void k_init() {
    int i = blockIdx.x*blockDim.x + threadIdx.x;
    if (i >= NN) return;
    g_deg[i]  = 2.0f;   // two self loops, weight 1 each
    g_icnt[i] = 0;
    g_ecnt[i] = 1;      // one CSR slot for the folded self loop
    g_efill[i]= 0;
    g_pfill[i]= 0;
    g_sumI[i*3+0] = 0.f; g_sumI[i*3+1] = 0.f; g_sumI[i*3+2] = 0.f;
}

// ---------------- pass 1: counts + image sums ----------------
__global__ void k_build1(const int* __restrict__ labels, const float* __restrict__ image) {
    int p = blockIdx.x*blockDim.x + threadIdx.x;
    if (p >= NPX) return;
    int b  = p / HWPX;
    int yx = p % HWPX;
    int s = b*NSP + labels[p];
    atomicAdd(&g_icnt[s], 1);
    atomicAdd(&g_sumI[s*3+0], image[(size_t)(b*3+0)*HWPX + yx]);
    atomicAdd(&g_sumI[s*3+1], image[(size_t)(b*3+1)*HWPX + yx]);
    atomicAdd(&g_sumI[s*3+2], image[(size_t)(b*3+2)*HWPX + yx]);
}

// ---------------- edges: weights + degree + per-dst counts ----------------
__global__ void k_edge_w_deg(const int* __restrict__ edges, const float* __restrict__ probas) {
    int e = blockIdx.x*blockDim.x + threadIdx.x;
    if (e >= EE) return;
    int src = edges[e], dst = edges[EE + e];
    float w = expf(-fabsf(probas[src] - probas[dst]) * SIGMA_INV);
    g_wnn[e] = w;
    atomicAdd(&g_deg[dst], w);
    atomicAdd(&g_ecnt[dst], 1);
}

// ---------------- scans (single block, 1024 thr, 6 elems each) ----------------
__global__ void k_scanE() {
    __shared__ int sm[1024];
    int t = threadIdx.x;
    int loc[6]; int s = 0;
    #pragma unroll
    for (int i = 0; i < 6; i++) {
        int idx = t*6 + i;
        int v = (idx < NN) ? g_ecnt[idx] : 0;
        loc[i] = s; s += v;
    }
    sm[t] = s; __syncthreads();
    for (int d = 1; d < 1024; d <<= 1) {
        int v = (t >= d) ? sm[t-d] : 0;
        __syncthreads();
        sm[t] += v;
        __syncthreads();
    }
    int base = (t > 0) ? sm[t-1] : 0;
    #pragma unroll
    for (int i = 0; i < 6; i++) {
        int idx = t*6 + i;
        if (idx < NN) g_eoff[idx] = base + loc[i];
    }
    if (t == 1023) g_eoff[NN] = sm[1023];
}

__global__ void k_scanP() {
    __shared__ int sm[1024];
    int t = threadIdx.x;
    int loc[6]; int s = 0;
    #pragma unroll
    for (int i = 0; i < 6; i++) {
        int idx = t*6 + i;
        int v = (idx < NN) ? 4*g_icnt[idx] : 0;
        loc[i] = s; s += v;
    }
    sm[t] = s; __syncthreads();
    for (int d = 1; d < 1024; d <<= 1) {
        int v = (t >= d) ? sm[t-d] : 0;
        __syncthreads();
        sm[t] += v;
        __syncthreads();
    }
    int base = (t > 0) ? sm[t-1] : 0;
    #pragma unroll
    for (int i = 0; i < 6; i++) {
        int idx = t*6 + i;
        if (idx < NN) g_poff[idx] = base + loc[i];
    }
    if (t == 1023) g_poff[NN] = sm[1023];
}

__global__ void k_dis() {
    int n = blockIdx.x*blockDim.x + threadIdx.x;
    if (n >= NN) return;
    float d = g_deg[n];
    g_dis[n] = (d > 0.f) ? rsqrtf(fmaxf(d, 1e-30f)) : 0.f;
    g_cnt[n] = (float)g_icnt[n];
}

// ---------------- edge CSR scatter ----------------
__global__ void k_edge_scatter(const int* __restrict__ edges) {
    int i = blockIdx.x*blockDim.x + threadIdx.x;
    if (i >= EE + NN) return;
    if (i < EE) {
        int src = edges[i], dst = edges[EE + i];
        float w = g_wnn[i];
        int j = g_eoff[dst] + atomicAdd(&g_efill[dst], 1);
        g_csr_src[j] = src;
        g_csr_nrm[j] = g_dis[src] * w * g_dis[dst];
    } else {
        int n = i - EE;
        int j = g_eoff[n] + atomicAdd(&g_efill[n], 1);
        g_csr_src[j] = n;
        g_csr_nrm[j] = 2.0f * g_dis[n] * g_dis[n];   // both self loops folded
    }
}

// ---------------- pass 2: pooling entries ----------------
__global__ void k_build2(const int* __restrict__ labels) {
    int p = blockIdx.x*blockDim.x + threadIdx.x;
    if (p >= NPX) return;
    int b  = p / HWPX;
    int yx = p % HWPX;
    int y = yx / HH, x = yx % HH;
    int s = b*NSP + labels[p];

    const float scale = 95.0f/383.0f;
    float fy = y*scale, fx = x*scale;
    int y0 = (int)floorf(fy); if (y0 > 95) y0 = 95;
    int x0 = (int)floorf(fx); if (x0 > 95) x0 = 95;
    float wy = fy - y0, wx = fx - x0;
    int y1 = min(y0+1, 95), x1 = min(x0+1, 95);

    int base = b*HWI;
    int pos = g_poff[s] + atomicAdd(&g_pfill[s], 4);
    int2 e0; e0.x = base + y0*HS + x0; e0.y = __float_as_int((1.f-wy)*(1.f-wx));
    int2 e1; e1.x = base + y0*HS + x1; e1.y = __float_as_int((1.f-wy)*wx);
    int2 e2; e2.x = base + y1*HS + x0; e2.y = __float_as_int(wy*(1.f-wx));
    int2 e3; e3.x = base + y1*HS + x1; e3.y = __float_as_int(wy*wx);
    g_ent[pos+0] = e0; g_ent[pos+1] = e1; g_ent[pos+2] = e2; g_ent[pos+3] = e3;
}

// ---------------- feats transpose NCHW(b,256,96,96) -> fp16 (b*9216, 512) ----------------
__global__ void k_transpose(const float* __restrict__ src, int colOff) {
    __shared__ float t[32][33];
    int b  = blockIdx.z;
    int q0 = blockIdx.x*32, c0 = blockIdx.y*32;
    int tx = threadIdx.x, ty = threadIdx.y;     // 32 x 8
    #pragma unroll
    for (int i = 0; i < 32; i += 8) {
        int c = c0 + ty + i, q = q0 + tx;
        t[ty+i][tx] = src[((size_t)b*CC + c)*HWI + q];
    }
    __syncthreads();
    #pragma unroll
    for (int i = 0; i < 32; i += 8) {
        int q = q0 + ty + i, c = c0 + tx;
        g_Bmh[((size_t)b*HWI + q)*NPOOL + colOff + c] = __float2half(t[tx][ty+i]);
    }
}

// ---------------- sparse pooling SpMM: one block per superpixel ----------------
// 256 threads; thread t owns output cols (2t, 2t+1) via one half2 load per entry.
__global__ void k_spmm() {
    __shared__ int2 sh[128];
    int s = blockIdx.x;
    int t = threadIdx.x;
    int beg = g_poff[s], end = g_poff[s+1];
    float ax0 = 0.f, ay0 = 0.f, ax1 = 0.f, ay1 = 0.f;
    const __half2* __restrict__ B2 = reinterpret_cast<const __half2*>(g_Bmh);

    for (int c0 = beg; c0 < end; c0 += 128) {
        int m = min(128, end - c0);
        __syncthreads();
        if (t < m) sh[t] = g_ent[c0 + t];
        __syncthreads();
        int j = 0;
        for (; j + 1 < m; j += 2) {
            int2 e0 = sh[j], e1 = sh[j+1];
            float w0 = __int_as_float(e0.y), w1 = __int_as_float(e1.y);
            float2 f0 = __half22float2(B2[(size_t)e0.x*256 + t]);
            float2 f1 = __half22float2(B2[(size_t)e1.x*256 + t]);
            ax0 = fmaf(w0, f0.x, ax0); ay0 = fmaf(w0, f0.y, ay0);
            ax1 = fmaf(w1, f1.x, ax1); ay1 = fmaf(w1, f1.y, ay1);
        }
        if (j < m) {
            int2 e0 = sh[j];
            float w0 = __int_as_float(e0.y);
            float2 f0 = __half22float2(B2[(size_t)e0.x*256 + t]);
            ax0 = fmaf(w0, f0.x, ax0); ay0 = fmaf(w0, f0.y, ay0);
        }
    }
    g_pool[(size_t)s*NPOOL + 2*t]     = ax0 + ax1;
    g_pool[(size_t)s*NPOOL + 2*t + 1] = ay0 + ay1;
}

// ---------------- generic SGEMM: C = A(MxK, row) * B(KxN, row) ----------------
// BM=128 BN=64 BK=8, 256 threads, 8x4 per-thread tile. K%8==0, N%64==0.
__global__ void k_sgemm(const float* __restrict__ A, const float* __restrict__ B,
                        float* __restrict__ C, int M, int N, int K,
                        int lda, int ldb, int ldc) {
    __shared__ float As[8][128];
    __shared__ float Bs[8][64];
    int tid = threadIdx.x;
    int tx = tid & 15, ty = tid >> 4;
    int m0 = blockIdx.y*128, n0 = blockIdx.x*64;
    float acc[8][4];
    #pragma unroll
    for (int i=0;i<8;i++)
        #pragma unroll
        for (int j=0;j<4;j++) acc[i][j]=0.f;

    int a_m = tid >> 1;          // 0..127
    int a_k = (tid & 1) * 4;     // 0 or 4
    int b_k = tid >> 5;          // 0..7
    int b_n = (tid & 31) * 2;    // 0..62

    for (int kt = 0; kt < K; kt += 8) {
        float4 av = make_float4(0.f,0.f,0.f,0.f);
        if (m0 + a_m < M)
            av = *reinterpret_cast<const float4*>(A + (size_t)(m0+a_m)*lda + kt + a_k);
        As[a_k+0][a_m]=av.x; As[a_k+1][a_m]=av.y;
        As[a_k+2][a_m]=av.z; As[a_k+3][a_m]=av.w;
        float2 bv = *reinterpret_cast<const float2*>(B + (size_t)(kt+b_k)*ldb + n0 + b_n);
        Bs[b_k][b_n]=bv.x; Bs[b_k][b_n+1]=bv.y;
        __syncthreads();
        #pragma unroll
        for (int k = 0; k < 8; k++) {
            float ar[8], br[4];
            #pragma unroll
            for (int i=0;i<8;i++) ar[i]=As[k][ty*8+i];
            #pragma unroll
            for (int j=0;j<4;j++) br[j]=Bs[k][tx*4+j];
            #pragma unroll
            for (int i=0;i<8;i++)
                #pragma unroll
                for (int j=0;j<4;j++) acc[i][j] = fmaf(ar[i], br[j], acc[i][j]);
        }
        __syncthreads();
    }
    #pragma unroll
    for (int i = 0; i < 8; i++) {
        int m = m0 + ty*8 + i;
        if (m < M) {
            #pragma unroll
            for (int j = 0; j < 4; j++)
                C[(size_t)m*ldc + n0 + tx*4 + j] = acc[i][j];
        }
    }
}

// ---------------- GCN ----------------
__global__ void k_x0(const float* __restrict__ W0) {   // xw = (sumI/cnt) @ W0  (K=3)
    __shared__ float z0[3];
    int n = blockIdx.x, c = threadIdx.x;
    if (c < 3) z0[c] = g_sumI[n*3+c] / fmaxf(g_cnt[n], 1.0f);
    __syncthreads();
    g_xw[(size_t)n*CC + c] = z0[0]*W0[c] + z0[1]*W0[CC+c] + z0[2]*W0[2*CC+c];
}

__global__ void k_agg_relu(const float* __restrict__ xw, const float* __restrict__ bias,
                           float* __restrict__ out) {
    int n = blockIdx.x, c = threadIdx.x;
    int s = g_eoff[n], e = g_eoff[n+1];
    float acc = 0.f;
    for (int j = s; j < e; j++) {
        int   sc = __ldg(&g_csr_src[j]);
        float nr = __ldg(&g_csr_nrm[j]);
        acc = fmaf(nr, __ldg(&xw[(size_t)sc*CC + c]), acc);
    }
    out[(size_t)n*CC + c] = fmaxf(acc + bias[c], 0.f);
}

__global__ void k_mix(const float* __restrict__ Zin, float* __restrict__ Zout, int colOff) {
    int n = blockIdx.x, c = threadIdx.x;
    float hp = g_pool[(size_t)n*NPOOL + colOff + c] / fmaxf(g_cnt[n], 1.0f);
    Zout[(size_t)n*CC + c] = 0.5f*hp + 0.5f*Zin[(size_t)n*CC + c];
}

// ---------------- epilogue ----------------
__global__ void k_norm_lin(const float* __restrict__ lin_w) {  // one block, 256 thr
    __shared__ float red[8];
    int c = threadIdx.x, lane = c & 31, w = c >> 5;
    for (int k = 0; k < 15; k++) {
        float v = lin_w[k*CC + c];
        float sq = v*v;
        #pragma unroll
        for (int o = 16; o > 0; o >>= 1) sq += __shfl_xor_sync(0xffffffffu, sq, o);
        if (lane == 0) red[w] = sq;
        __syncthreads();
        float tot = 0.f;
        #pragma unroll
        for (int i = 0; i < 8; i++) tot += red[i];
        g_wn[k*CC + c] = v / sqrtf(tot);
        __syncthreads();
    }
}

__global__ void k_out(const float* __restrict__ Z, float* __restrict__ outp) {
    __shared__ float sh[CC];
    __shared__ float red[8];
    int n = blockIdx.x, c = threadIdx.x;
    int lane = c & 31, w = c >> 5;
    float z = Z[(size_t)n*CC + c];
    float sq = z*z;
    #pragma unroll
    for (int o = 16; o > 0; o >>= 1) sq += __shfl_xor_sync(0xffffffffu, sq, o);
    if (lane == 0) red[w] = sq;
    __syncthreads();
    float tot = 0.f;
    #pragma unroll
    for (int i = 0; i < 8; i++) tot += red[i];
    float nrm = fmaxf(sqrtf(tot), 1e-12f);
    float v = z / nrm;
    outp[(size_t)NN*15 + (size_t)n*CC + c] = v;   // cs_r
    sh[c] = v;
    __syncthreads();
    for (int k = w; k < 15; k += 8) {
        float d = 0.f;
        for (int i = lane; i < CC; i += 32) d = fmaf(sh[i], g_wn[k*CC + i], d);
        #pragma unroll
        for (int o = 16; o > 0; o >>= 1) d += __shfl_xor_sync(0xffffffffu, d, o);
        if (lane == 0) outp[(size_t)n*15 + k] = d;   // cs
    }
}

// ---------------- launch ----------------
extern "C" void kernel_launch(void* const* d_in, const int* in_sizes, int n_in,
                              void* d_out, int out_size) {
    const float* image  = (const float*)d_in[0];
    const int*   labels = (const int*)  d_in[1];
    const int*   edges  = (const int*)  d_in[2];
    const float* probas = (const float*)d_in[3];
    const float* feats0 = (const float*)d_in[4];
    const float* feats1 = (const float*)d_in[5];
    const float* W0     = (const float*)d_in[6];
    const float* b0     = (const float*)d_in[7];
    const float* W1     = (const float*)d_in[8];
    const float* b1     = (const float*)d_in[9];
    const float* W2     = (const float*)d_in[10];
    const float* b2     = (const float*)d_in[11];
    const float* lin_w  = (const float*)d_in[12];
    float* outp = (float*)d_out;

    float *pZa, *pZb, *pXw;
    cudaGetSymbolAddress((void**)&pZa, g_Za);
    cudaGetSymbolAddress((void**)&pZb, g_Zb);
    cudaGetSymbolAddress((void**)&pXw, g_xw);

    k_init<<<(NN+255)/256, 256>>>();
    k_build1<<<NPX/256, 256>>>(labels, image);
    k_edge_w_deg<<<(EE+255)/256, 256>>>(edges, probas);

    dim3 tg(HWI/32, CC/32, BB), tb(32, 8);
    k_transpose<<<tg, tb>>>(feats0, 0);
    k_transpose<<<tg, tb>>>(feats1, CC);

    k_scanE<<<1, 1024>>>();
    k_scanP<<<1, 1024>>>();
    k_dis<<<(NN+255)/256, 256>>>();
    k_edge_scatter<<<(EE+NN+255)/256, 256>>>(edges);
    k_build2<<<NPX/256, 256>>>(labels);

    k_spmm<<<NN, 256>>>();

    // layer 1: image-pooled features
    k_x0<<<NN, CC>>>(W0);
    k_agg_relu<<<NN, CC>>>(pXw, b0, pZa);

    // layer 2: feats0
    k_mix<<<NN, CC>>>(pZa, pZb, 0);
    k_sgemm<<<dim3(CC/64, (NN+127)/128, 1), 256>>>(pZb, W1, pXw, NN, CC, CC, CC, CC, CC);
    k_agg_relu<<<NN, CC>>>(pXw, b1, pZa);

    // layer 3: feats1
    k_mix<<<NN, CC>>>(pZa, pZb, CC);
    k_sgemm<<<dim3(CC/64, (NN+127)/128, 1), 256>>>(pZb, W2, pXw, NN, CC, CC, CC, CC, CC);
    k_agg_relu<<<NN, CC>>>(pXw, b2, pZa);

    k_norm_lin<<<1, CC>>>(lin_w);
    k_out<<<NN, CC>>>(pZa, outp);
    (void)in_sizes; (void)n_in; (void)out_size;
}

// round 5
// speedup vs baseline: 1.3952x; 1.3952x over previous
#include <cuda_runtime.h>
#include <cuda_fp16.h>
#include <math.h>
#include <stdint.h>

// ---------------- problem constants ----------------
#define BB   4
#define NSP  1500
#define NN   6000          // BB*NSP
#define EE   120000
#define HH   384
#define HWPX (HH*HH)       // 147456
#define NPX  (BB*HWPX)     // 589824
#define HS   96
#define HWI  (HS*HS)       // 9216
#define CC   256
#define NPOOL 512          // feats0 | feats1 columns
#define NENT (4*NPX)       // 2359296 pooling entries
#define CSR_E (EE+NN)      // folded self loops: one entry each, weight 2*dis^2
#define SIGMA_INV 5.0f     // 1/0.2

// ---------------- scratch (device globals; k_init re-inits every call) ----------
__device__ __half g_Bmh[(size_t)BB*HWI*NPOOL];   // 37.7 MB feats NHWC fp16, stacked
__device__ int4  g_ent4[NENT/2];                 // packed (row,w) pairs, 18.9 MB
__device__ float g_pool[(size_t)NN*NPOOL];
__device__ float g_Za[NN*CC];
__device__ float g_Zb[NN*CC];
__device__ float g_xw[NN*CC];
__device__ float g_cnt[NN];
__device__ float g_sumI[NN*3];
__device__ float g_deg[NN];      // self-loop +2 folded into dis computation
__device__ float g_dis[NN];
__device__ float g_wnn[EE];
__device__ int   g_icnt[NN];
__device__ int   g_ecnt[NN];     // +1 self slot folded into scanE
__device__ int   g_eoff[NN+1];
__device__ int   g_poff[NN+1];
__device__ int   g_efill[NN];
__device__ int   g_pfill[NN];
__device__ int   g_csr_src[CSR_E];
__device__ float g_csr_nrm[CSR_E];
__device__ float g_wn[15*CC];

// ---------------- 0: init (self-healing regardless of prior stream state) -------
__global__ void k_init() {
    int i = blockIdx.x*blockDim.x + threadIdx.x;
    if (i >= NN) return;
    g_icnt[i] = 0; g_ecnt[i] = 0;
    g_efill[i] = 0; g_pfill[i] = 0;
    g_deg[i] = 0.f;
    g_sumI[i*3+0] = 0.f; g_sumI[i*3+1] = 0.f; g_sumI[i*3+2] = 0.f;
}

// ---------------- 1: counts + image sums ----------------
__global__ void k_build1(const int* __restrict__ labels, const float* __restrict__ image) {
    int p = blockIdx.x*blockDim.x + threadIdx.x;
    if (p >= NPX) return;
    int b  = p / HWPX;
    int yx = p % HWPX;
    int s = b*NSP + labels[p];
    atomicAdd(&g_icnt[s], 1);
    atomicAdd(&g_sumI[s*3+0], image[(size_t)(b*3+0)*HWPX + yx]);
    atomicAdd(&g_sumI[s*3+1], image[(size_t)(b*3+1)*HWPX + yx]);
    atomicAdd(&g_sumI[s*3+2], image[(size_t)(b*3+2)*HWPX + yx]);
}

// ---------------- 2: feats transpose NCHW -> fp16 (b*9216, 512), both tensors ----
__global__ void k_transpose(const float* __restrict__ f0, const float* __restrict__ f1) {
    __shared__ float t[32][33];
    int z = blockIdx.z;                 // 0..7
    int b = z & 3;
    int colOff = (z >> 2) * CC;
    const float* __restrict__ src = (z < 4) ? f0 : f1;
    int q0 = blockIdx.x*32, c0 = blockIdx.y*32;
    int tx = threadIdx.x, ty = threadIdx.y;     // 32 x 8
    #pragma unroll
    for (int i = 0; i < 32; i += 8) {
        int c = c0 + ty + i, q = q0 + tx;
        t[ty+i][tx] = src[((size_t)b*CC + c)*HWI + q];
    }
    __syncthreads();
    #pragma unroll
    for (int i = 0; i < 32; i += 8) {
        int q = q0 + ty + i, c = c0 + tx;
        g_Bmh[((size_t)b*HWI + q)*NPOOL + colOff + c] = __float2half(t[tx][ty+i]);
    }
}

// ---------------- 3: scan pooling counts (+cnt float) ----------------
__global__ void k_scanP() {
    __shared__ int sm[1024];
    int t = threadIdx.x;
    int loc[6]; int s = 0;
    #pragma unroll
    for (int i = 0; i < 6; i++) {
        int idx = t*6 + i;
        int v = (idx < NN) ? 4*g_icnt[idx] : 0;
        loc[i] = s; s += v;
        if (idx < NN) g_cnt[idx] = (float)g_icnt[idx];
    }
    sm[t] = s; __syncthreads();
    for (int d = 1; d < 1024; d <<= 1) {
        int v = (t >= d) ? sm[t-d] : 0;
        __syncthreads();
        sm[t] += v;
        __syncthreads();
    }
    int base = (t > 0) ? sm[t-1] : 0;
    #pragma unroll
    for (int i = 0; i < 6; i++) {
        int idx = t*6 + i;
        if (idx < NN) g_poff[idx] = base + loc[i];
    }
    if (t == 1023) g_poff[NN] = sm[1023];
}

// ---------------- 4: pooling entries (CSR by superpixel) ----------------
__global__ void k_build2(const int* __restrict__ labels) {
    int p = blockIdx.x*blockDim.x + threadIdx.x;
    if (p >= NPX) return;
    int b  = p / HWPX;
    int yx = p % HWPX;
    int y = yx / HH, x = yx % HH;
    int s = b*NSP + labels[p];

    const float scale = 95.0f/383.0f;
    float fy = y*scale, fx = x*scale;
    int y0 = (int)floorf(fy); if (y0 > 95) y0 = 95;
    int x0 = (int)floorf(fx); if (x0 > 95) x0 = 95;
    float wy = fy - y0, wx = fx - x0;
    int y1 = min(y0+1, 95), x1 = min(x0+1, 95);

    int base = b*HWI;
    int pos = g_poff[s] + atomicAdd(&g_pfill[s], 4);   // pos % 4 == 0
    int4 a, bb;
    a.x  = base + y0*HS + x0;  a.y  = __float_as_int((1.f-wy)*(1.f-wx));
    a.z  = base + y0*HS + x1;  a.w  = __float_as_int((1.f-wy)*wx);
    bb.x = base + y1*HS + x0;  bb.y = __float_as_int(wy*(1.f-wx));
    bb.z = base + y1*HS + x1;  bb.w = __float_as_int(wy*wx);
    g_ent4[(pos>>1)+0] = a;
    g_ent4[(pos>>1)+1] = bb;
}

// ---------------- 5/6: sparse pooling SpMM ----------------
// 256 thr = 4 teams x 64 lanes; lane owns 8 cols via one uint4 (8 fp16) load.
__device__ __forceinline__ void acc8(float* acc, float w, uint4 v) {
    float2 f0 = __half22float2(*(const __half2*)&v.x);
    float2 f1 = __half22float2(*(const __half2*)&v.y);
    float2 f2 = __half22float2(*(const __half2*)&v.z);
    float2 f3 = __half22float2(*(const __half2*)&v.w);
    acc[0] = fmaf(w, f0.x, acc[0]); acc[1] = fmaf(w, f0.y, acc[1]);
    acc[2] = fmaf(w, f1.x, acc[2]); acc[3] = fmaf(w, f1.y, acc[3]);
    acc[4] = fmaf(w, f2.x, acc[4]); acc[5] = fmaf(w, f2.y, acc[5]);
    acc[6] = fmaf(w, f3.x, acc[6]); acc[7] = fmaf(w, f3.y, acc[7]);
}

__global__ void k_spmm(int s0) {
    __shared__ int2  sh[256];
    __shared__ float red[4][512];
    int s = blockIdx.x + s0;
    int tid = threadIdx.x;
    int team = tid >> 6, lane = tid & 63;
    int beg = g_poff[s], end = g_poff[s+1];
    const uint4* __restrict__ B4 = reinterpret_cast<const uint4*>(g_Bmh);
    const int2* __restrict__ ent = reinterpret_cast<const int2*>(g_ent4);
    float acc[8];
    #pragma unroll
    for (int i = 0; i < 8; i++) acc[i] = 0.f;

    for (int c0 = beg; c0 < end; c0 += 256) {
        int m = min(256, end - c0);
        __syncthreads();
        if (tid < m) sh[tid] = ent[c0 + tid];
        __syncthreads();
        int j = team;
        for (; j + 4 < m; j += 8) {
            int2 e0 = sh[j], e1 = sh[j+4];
            uint4 v0 = B4[(size_t)e0.x*64 + lane];
            uint4 v1 = B4[(size_t)e1.x*64 + lane];
            acc8(acc, __int_as_float(e0.y), v0);
            acc8(acc, __int_as_float(e1.y), v1);
        }
        if (j < m) {
            int2 e0 = sh[j];
            uint4 v0 = B4[(size_t)e0.x*64 + lane];
            acc8(acc, __int_as_float(e0.y), v0);
        }
    }
    #pragma unroll
    for (int i = 0; i < 8; i++) red[team][lane*8+i] = acc[i];
    __syncthreads();
    #pragma unroll
    for (int c = tid; c < 512; c += 256)
        g_pool[(size_t)s*NPOOL + c] = red[0][c] + red[1][c] + red[2][c] + red[3][c];
}

// ---------------- 7: edge weights + degree + per-dst counts ----------------
__global__ void k_edge_w_deg(const int* __restrict__ edges, const float* __restrict__ probas) {
    int e = blockIdx.x*blockDim.x + threadIdx.x;
    if (e >= EE) return;
    int src = edges[e], dst = edges[EE + e];
    float w = expf(-fabsf(probas[src] - probas[dst]) * SIGMA_INV);
    g_wnn[e] = w;
    atomicAdd(&g_deg[dst], w);
    atomicAdd(&g_ecnt[dst], 1);
}

// ---------------- 8: scan edge counts (+1 self slot) and dis ----------------
__global__ void k_scanE() {
    __shared__ int sm[1024];
    int t = threadIdx.x;
    int loc[6]; int s = 0;
    #pragma unroll
    for (int i = 0; i < 6; i++) {
        int idx = t*6 + i;
        int v = (idx < NN) ? (g_ecnt[idx] + 1) : 0;
        loc[i] = s; s += v;
        if (idx < NN) {
            float d = g_deg[idx] + 2.0f;
            g_dis[idx] = rsqrtf(fmaxf(d, 1e-30f));
        }
    }
    sm[t] = s; __syncthreads();
    for (int d = 1; d < 1024; d <<= 1) {
        int v = (t >= d) ? sm[t-d] : 0;
        __syncthreads();
        sm[t] += v;
        __syncthreads();
    }
    int base = (t > 0) ? sm[t-1] : 0;
    #pragma unroll
    for (int i = 0; i < 6; i++) {
        int idx = t*6 + i;
        if (idx < NN) g_eoff[idx] = base + loc[i];
    }
    if (t == 1023) g_eoff[NN] = sm[1023];
}

// ---------------- 9: edge CSR scatter (self loop -> last slot, no atomic) ------
__global__ void k_edge_scatter(const int* __restrict__ edges) {
    int i = blockIdx.x*blockDim.x + threadIdx.x;
    if (i >= EE + NN) return;
    if (i < EE) {
        int src = edges[i], dst = edges[EE + i];
        float w = g_wnn[i];
        int j = g_eoff[dst] + atomicAdd(&g_efill[dst], 1);
        g_csr_src[j] = src;
        g_csr_nrm[j] = g_dis[src] * w * g_dis[dst];
    } else {
        int n = i - EE;
        int j = g_eoff[n+1] - 1;
        g_csr_src[j] = n;
        g_csr_nrm[j] = 2.0f * g_dis[n] * g_dis[n];
    }
}

// ---------------- GCN ----------------
__global__ void k_x0(const float* __restrict__ W0) {   // xw = (sumI/cnt) @ W0 (K=3)
    __shared__ float z0[3];
    int n = blockIdx.x, c = threadIdx.x;
    if (c < 3) z0[c] = g_sumI[n*3+c] / fmaxf(g_cnt[n], 1.0f);
    __syncthreads();
    g_xw[(size_t)n*CC + c] = z0[0]*W0[c] + z0[1]*W0[CC+c] + z0[2]*W0[2*CC+c];
}

// 256 thr = 4 teams x 64 lanes; lane owns 4 cols via float4. grid = NN/4.
__global__ void k_agg_relu(const float* __restrict__ xw, const float* __restrict__ bias,
                           float* __restrict__ out) {
    int tid = threadIdx.x;
    int team = tid >> 6, lane = tid & 63;
    int n = blockIdx.x*4 + team;
    const float4* __restrict__ xw4 = reinterpret_cast<const float4*>(xw);
    float4 bv = reinterpret_cast<const float4*>(bias)[lane];
    int s = g_eoff[n], e = g_eoff[n+1];
    float4 acc = make_float4(0.f,0.f,0.f,0.f);
    for (int j = s; j < e; j++) {
        int   sc = __ldg(&g_csr_src[j]);
        float nr = __ldg(&g_csr_nrm[j]);
        float4 v = xw4[(size_t)sc*64 + lane];
        acc.x = fmaf(nr, v.x, acc.x); acc.y = fmaf(nr, v.y, acc.y);
        acc.z = fmaf(nr, v.z, acc.z); acc.w = fmaf(nr, v.w, acc.w);
    }
    float4 r;
    r.x = fmaxf(acc.x + bv.x, 0.f); r.y = fmaxf(acc.y + bv.y, 0.f);
    r.z = fmaxf(acc.z + bv.z, 0.f); r.w = fmaxf(acc.w + bv.w, 0.f);
    reinterpret_cast<float4*>(out)[(size_t)n*64 + lane] = r;
}

// grid 1500 x 256 thr, float4 per thread
__global__ void k_mix(const float* __restrict__ Zin, float* __restrict__ Zout, int off4) {
    int i = blockIdx.x*256 + threadIdx.x;          // 0..383999
    int n = i >> 6, c4 = i & 63;
    float4 hp = reinterpret_cast<const float4*>(g_pool)[(size_t)n*128 + off4 + c4];
    float4 z  = reinterpret_cast<const float4*>(Zin)[(size_t)n*64 + c4];
    float inv = 0.5f / fmaxf(g_cnt[n], 1.0f);
    float4 r;
    r.x = hp.x*inv + 0.5f*z.x; r.y = hp.y*inv + 0.5f*z.y;
    r.z = hp.z*inv + 0.5f*z.z; r.w = hp.w*inv + 0.5f*z.w;
    reinterpret_cast<float4*>(Zout)[(size_t)n*64 + c4] = r;
}

// ---------------- SGEMM: C = A(MxK) * B(KxN), row-major, BM=128 BN=64 BK=8 ------
__global__ void k_sgemm(const float* __restrict__ A, const float* __restrict__ B,
                        float* __restrict__ C, int M, int N, int K,
                        int lda, int ldb, int ldc) {
    __shared__ float As[8][128];
    __shared__ float Bs[8][64];
    int tid = threadIdx.x;
    int tx = tid & 15, ty = tid >> 4;
    int m0 = blockIdx.y*128, n0 = blockIdx.x*64;
    float acc[8][4];
    #pragma unroll
    for (int i=0;i<8;i++)
        #pragma unroll
        for (int j=0;j<4;j++) acc[i][j]=0.f;

    int a_m = tid >> 1;
    int a_k = (tid & 1) * 4;
    int b_k = tid >> 5;
    int b_n = (tid & 31) * 2;

    for (int kt = 0; kt < K; kt += 8) {
        float4 av = make_float4(0.f,0.f,0.f,0.f);
        if (m0 + a_m < M)
            av = *reinterpret_cast<const float4*>(A + (size_t)(m0+a_m)*lda + kt + a_k);
        As[a_k+0][a_m]=av.x; As[a_k+1][a_m]=av.y;
        As[a_k+2][a_m]=av.z; As[a_k+3][a_m]=av.w;
        float2 bv = *reinterpret_cast<const float2*>(B + (size_t)(kt+b_k)*ldb + n0 + b_n);
        Bs[b_k][b_n]=bv.x; Bs[b_k][b_n+1]=bv.y;
        __syncthreads();
        #pragma unroll
        for (int k = 0; k < 8; k++) {
            float ar[8], br[4];
            #pragma unroll
            for (int i=0;i<8;i++) ar[i]=As[k][ty*8+i];
            #pragma unroll
            for (int j=0;j<4;j++) br[j]=Bs[k][tx*4+j];
            #pragma unroll
            for (int i=0;i<8;i++)
                #pragma unroll
                for (int j=0;j<4;j++) acc[i][j] = fmaf(ar[i], br[j], acc[i][j]);
        }
        __syncthreads();
    }
    #pragma unroll
    for (int i = 0; i < 8; i++) {
        int m = m0 + ty*8 + i;
        if (m < M) {
            #pragma unroll
            for (int j = 0; j < 4; j++)
                C[(size_t)m*ldc + n0 + tx*4 + j] = acc[i][j];
        }
    }
}

// ---------------- epilogue ----------------
__global__ void k_norm_lin(const float* __restrict__ lin_w) {  // one block, 256 thr
    __shared__ float red[8];
    int c = threadIdx.x, lane = c & 31, w = c >> 5;
    for (int k = 0; k < 15; k++) {
        float v = lin_w[k*CC + c];
        float sq = v*v;
        #pragma unroll
        for (int o = 16; o > 0; o >>= 1) sq += __shfl_xor_sync(0xffffffffu, sq, o);
        if (lane == 0) red[w] = sq;
        __syncthreads();
        float tot = 0.f;
        #pragma unroll
        for (int i = 0; i < 8; i++) tot += red[i];
        g_wn[k*CC + c] = v / sqrtf(tot);
        __syncthreads();
    }
}

__global__ void k_out(const float* __restrict__ Z, float* __restrict__ outp) {
    __shared__ float sh[CC];
    __shared__ float red[8];
    int n = blockIdx.x, c = threadIdx.x;
    int lane = c & 31, w = c >> 5;
    float z = Z[(size_t)n*CC + c];
    float sq = z*z;
    #pragma unroll
    for (int o = 16; o > 0; o >>= 1) sq += __shfl_xor_sync(0xffffffffu, sq, o);
    if (lane == 0) red[w] = sq;
    __syncthreads();
    float tot = 0.f;
    #pragma unroll
    for (int i = 0; i < 8; i++) tot += red[i];
    float nrm = fmaxf(sqrtf(tot), 1e-12f);
    float v = z / nrm;
    outp[(size_t)NN*15 + (size_t)n*CC + c] = v;   // cs_r
    sh[c] = v;
    __syncthreads();
    for (int k = w; k < 15; k += 8) {
        float d = 0.f;
        for (int i = lane; i < CC; i += 32) d = fmaf(sh[i], g_wn[k*CC + i], d);
        #pragma unroll
        for (int o = 16; o > 0; o >>= 1) d += __shfl_xor_sync(0xffffffffu, d, o);
        if (lane == 0) outp[(size_t)n*15 + k] = d;   // cs
    }
}

// ---------------- launch ----------------
extern "C" void kernel_launch(void* const* d_in, const int* in_sizes, int n_in,
                              void* d_out, int out_size) {
    const float* image  = (const float*)d_in[0];
    const int*   labels = (const int*)  d_in[1];
    const int*   edges  = (const int*)  d_in[2];
    const float* probas = (const float*)d_in[3];
    const float* feats0 = (const float*)d_in[4];
    const float* feats1 = (const float*)d_in[5];
    const float* W0     = (const float*)d_in[6];
    const float* b0     = (const float*)d_in[7];
    const float* W1     = (const float*)d_in[8];
    const float* b1     = (const float*)d_in[9];
    const float* W2     = (const float*)d_in[10];
    const float* b2     = (const float*)d_in[11];
    const float* lin_w  = (const float*)d_in[12];
    float* outp = (float*)d_out;

    float *pZa, *pZb, *pXw;
    cudaGetSymbolAddress((void**)&pZa, g_Za);
    cudaGetSymbolAddress((void**)&pZb, g_Zb);
    cudaGetSymbolAddress((void**)&pXw, g_xw);

    // 0-4: init + pooling build
    k_init<<<(NN+255)/256, 256>>>();
    k_build1<<<NPX/256, 256>>>(labels, image);
    k_transpose<<<dim3(HWI/32, CC/32, 8), dim3(32, 8)>>>(feats0, feats1);
    k_scanP<<<1, 1024>>>();
    k_build2<<<NPX/256, 256>>>(labels);
    // 6-7: the heavy SpMM (positioned for ncu capture)
    k_spmm<<<NN/2, 256>>>(0);
    k_spmm<<<NN/2, 256>>>(NN/2);
    // 8-10: graph build
    k_edge_w_deg<<<(EE+255)/256, 256>>>(edges, probas);
    k_scanE<<<1, 1024>>>();
    k_edge_scatter<<<(EE+NN+255)/256, 256>>>(edges);
    // 11-12: layer 1 (image)
    k_x0<<<NN, CC>>>(W0);
    k_agg_relu<<<NN/4, 256>>>(pXw, b0, pZa);
    // 13-15: layer 2 (feats0)
    k_mix<<<1500, 256>>>(pZa, pZb, 0);
    k_sgemm<<<dim3(CC/64, (NN+127)/128, 1), 256>>>(pZb, W1, pXw, NN, CC, CC, CC, CC, CC);
    k_agg_relu<<<NN/4, 256>>>(pXw, b1, pZa);
    // 16-18: layer 3 (feats1)
    k_mix<<<1500, 256>>>(pZa, pZb, 64);
    k_sgemm<<<dim3(CC/64, (NN+127)/128, 1), 256>>>(pZb, W2, pXw, NN, CC, CC, CC, CC, CC);
    k_agg_relu<<<NN/4, 256>>>(pXw, b2, pZa);
    // 19-20: epilogue
    k_norm_lin<<<1, CC>>>(lin_w);
    k_out<<<NN, CC>>>(pZa, outp);
    (void)in_sizes; (void)n_in; (void)out_size;
}